// round 5
// baseline (speedup 1.0000x reference)
#include <cuda_runtime.h>

#define Bn 32
#define Nn 1024
#define Cn 768
#define C4 192        // Cn / 4
#define ORBITS 272
#define GRID (Bn * ORBITS)  // 8704

// Scratch (no allocation allowed in kernel_launch)
__device__ float g_pdot[GRID * 4];   // per-orbit partial dot with W
__device__ float g_alpha[Bn * 4];    // per-batch merge coefficients
__device__ int   g_cnt[Bn];          // completion tickets
__device__ int   g_flag[Bn];         // alpha-ready flags

__global__ void reset_kernel() {
    int t = threadIdx.x;
    if (t < Bn) { g_cnt[t] = 0; g_flag[t] = 0; }
}

// One block per orbit {l, tl, rl, rtl}. Orbits partition the 1024 rows of a
// batch, so each block's 4 loaded rows double as its pooling contribution.
__global__ void __launch_bounds__(192) fused_kernel(
    const float* __restrict__ x,
    const float* __restrict__ W,
    const float* __restrict__ bias,
    float* __restrict__ out) {
    int tid = threadIdx.x;  // 0..191
    int b = blockIdx.x / ORBITS;
    int o = blockIdx.x % ORBITS;
    int i = 0, cnt = 32;
    while (o >= cnt) { o -= cnt; i++; cnt -= 2; }
    int j = i + o;  // i <= j <= 31-i

    int l   = (i << 5) | j;
    int tl  = (j << 5) | i;
    int rl  = 1023 - l;
    int rtl = 1023 - tl;

    const float4* xb = (const float4*)(x + (size_t)b * Nn * Cn);
    float4*       ob = (float4*)(out + (size_t)b * Nn * Cn);

    // ── load the orbit's rows ONCE (streaming; no reuse chip-wide) ──
    float4 v0 = __ldcs(&xb[(size_t)l   * C4 + tid]);
    float4 v1 = __ldcs(&xb[(size_t)tl  * C4 + tid]);
    float4 v2 = __ldcs(&xb[(size_t)rl  * C4 + tid]);
    float4 v3 = __ldcs(&xb[(size_t)rtl * C4 + tid]);

    // ── pooling contribution: count DISTINCT rows once ──
    // i==j:    tl==l,  rtl==rl  -> weights (1,0,1,0)
    // j==31-i: rl==tl, rtl==l   -> weights (1,1,0,0)
    float w1 = (i == j) ? 0.f : 1.f;
    float w2 = (j == 31 - i) ? 0.f : 1.f;
    float w3 = (i == j || j == 31 - i) ? 0.f : 1.f;
    float4 ps;
    ps.x = v0.x + w1 * v1.x + w2 * v2.x + w3 * v3.x;
    ps.y = v0.y + w1 * v1.y + w2 * v2.y + w3 * v3.y;
    ps.z = v0.z + w1 * v1.z + w2 * v2.z + w3 * v3.z;
    ps.w = v0.w + w1 * v1.w + w2 * v2.w + w3 * v3.w;

    // per-thread dot with W rows (thread owns channels 4*tid..4*tid+3)
    float d[4];
#pragma unroll
    for (int k = 0; k < 4; k++) {
        float4 w4 = __ldg(&((const float4*)W)[k * C4 + tid]);
        d[k] = ps.x * w4.x + ps.y * w4.y + ps.z * w4.z + ps.w * w4.w;
    }
    // block reduce 4 values over 6 warps
    __shared__ float sdot[6][4];
    int lane = tid & 31, wid = tid >> 5;
#pragma unroll
    for (int k = 0; k < 4; k++) {
#pragma unroll
        for (int off = 16; off > 0; off >>= 1)
            d[k] += __shfl_down_sync(0xffffffffu, d[k], off);
        if (lane == 0) sdot[wid][k] = d[k];
    }
    __syncthreads();
    if (tid < 32) {
        int k = tid & 3, w = tid >> 2;  // w = 0..7 (pad >5 with 0)
        float v = (w < 6) ? sdot[w][k] : 0.f;
        v += __shfl_down_sync(0xffffffffu, v, 16);
        v += __shfl_down_sync(0xffffffffu, v, 8);
        v += __shfl_down_sync(0xffffffffu, v, 4);
        if (tid < 4)
            __stcg(&g_pdot[(size_t)blockIdx.x * 4 + k], v);
    }

    // ── ticket; last orbit block of the batch finalizes alpha[b] ──
    __shared__ int ticket;
    __threadfence();
    __syncthreads();
    if (tid == 0) ticket = atomicAdd(&g_cnt[b], 1);
    __syncthreads();
    if (ticket == ORBITS - 1) {
        if (tid < 128) {  // warp w reduces k=w over 272 orbit slots
            int k = tid >> 5;
            int ln = tid & 31;
            float s = 0.f;
#pragma unroll
            for (int m = 0; m < 9; m++) {
                int oo = ln + 32 * m;
                if (oo < ORBITS)
                    s += __ldcg(&g_pdot[((size_t)b * ORBITS + oo) * 4 + k]);
            }
#pragma unroll
            for (int off = 16; off > 0; off >>= 1)
                s += __shfl_down_sync(0xffffffffu, s, off);
            if (ln == 0)
                __stcg(&g_alpha[b * 4 + k], s * (1.0f / 1024.0f) + __ldg(&bias[k]));
        }
        __threadfence();
        __syncthreads();
        if (tid == 0) atomicExch(&g_flag[b], 1);
    }

    // ── wait for alpha (data already in registers) ──
    if (tid == 0) {
        while (atomicAdd(&g_flag[b], 0) == 0)
            __nanosleep(64);
    }
    __syncthreads();
    __threadfence();

    float c0 = __ldcg(&g_alpha[b * 4 + 0]);
    float c1 = __ldcg(&g_alpha[b * 4 + 1]);
    float c2 = __ldcg(&g_alpha[b * 4 + 2]);
    float c3 = __ldcg(&g_alpha[b * 4 + 3]);

    float4 w;
    // out[l] = c0 v0 + c1 v1 + c2 v2 + c3 v3
    w.x = fmaf(c0, v0.x, fmaf(c1, v1.x, fmaf(c2, v2.x, c3 * v3.x)));
    w.y = fmaf(c0, v0.y, fmaf(c1, v1.y, fmaf(c2, v2.y, c3 * v3.y)));
    w.z = fmaf(c0, v0.z, fmaf(c1, v1.z, fmaf(c2, v2.z, c3 * v3.z)));
    w.w = fmaf(c0, v0.w, fmaf(c1, v1.w, fmaf(c2, v2.w, c3 * v3.w)));
    __stcs(&ob[(size_t)l * C4 + tid], w);

    // out[tl] = c0 v1 + c1 v0 + c2 v3 + c3 v2
    w.x = fmaf(c0, v1.x, fmaf(c1, v0.x, fmaf(c2, v3.x, c3 * v2.x)));
    w.y = fmaf(c0, v1.y, fmaf(c1, v0.y, fmaf(c2, v3.y, c3 * v2.y)));
    w.z = fmaf(c0, v1.z, fmaf(c1, v0.z, fmaf(c2, v3.z, c3 * v2.z)));
    w.w = fmaf(c0, v1.w, fmaf(c1, v0.w, fmaf(c2, v3.w, c3 * v2.w)));
    __stcs(&ob[(size_t)tl * C4 + tid], w);

    // out[rl] = c0 v2 + c1 v3 + c2 v0 + c3 v1
    w.x = fmaf(c0, v2.x, fmaf(c1, v3.x, fmaf(c2, v0.x, c3 * v1.x)));
    w.y = fmaf(c0, v2.y, fmaf(c1, v3.y, fmaf(c2, v0.y, c3 * v1.y)));
    w.z = fmaf(c0, v2.z, fmaf(c1, v3.z, fmaf(c2, v0.z, c3 * v1.z)));
    w.w = fmaf(c0, v2.w, fmaf(c1, v3.w, fmaf(c2, v0.w, c3 * v1.w)));
    __stcs(&ob[(size_t)rl * C4 + tid], w);

    // out[rtl] = c0 v3 + c1 v2 + c2 v1 + c3 v0
    w.x = fmaf(c0, v3.x, fmaf(c1, v2.x, fmaf(c2, v1.x, c3 * v0.x)));
    w.y = fmaf(c0, v3.y, fmaf(c1, v2.y, fmaf(c2, v1.y, c3 * v0.y)));
    w.z = fmaf(c0, v3.z, fmaf(c1, v2.z, fmaf(c2, v1.z, c3 * v0.z)));
    w.w = fmaf(c0, v3.w, fmaf(c1, v2.w, fmaf(c2, v1.w, c3 * v0.w)));
    __stcs(&ob[(size_t)rtl * C4 + tid], w);
}

extern "C" void kernel_launch(void* const* d_in, const int* in_sizes, int n_in,
                              void* d_out, int out_size) {
    const float* x    = (const float*)d_in[0];  // (32,1024,768)
    const float* W    = (const float*)d_in[1];  // (4,768)
    const float* bias = (const float*)d_in[2];  // (4,)
    float* out = (float*)d_out;

    reset_kernel<<<1, 64>>>();
    fused_kernel<<<GRID, 192>>>(x, W, bias, out);
}

// round 6
// speedup vs baseline: 1.4829x; 1.4829x over previous
#include <cuda_runtime.h>

#define Bn 32
#define Nn 1024
#define Cn 768
#define C4 192
#define OPB 8               // orbits per block
#define BPB 34              // blocks per batch (272/8)
#define GRID (Bn * BPB)     // 1088

__device__ float g_pdot[GRID * 4];   // per-block partial dot with W
__device__ float g_alpha[Bn * 4];
__device__ int   g_cnt[Bn];
__device__ int   g_flag[Bn];

__global__ void reset_kernel() {
    int t = threadIdx.x;
    if (t < Bn) { g_cnt[t] = 0; g_flag[t] = 0; }
}

// Orbits {l, t(l), 1023-l, 1023-t(l)} partition each batch's 1024 rows.
// A block loads 8 orbits (32 rows) into registers ONCE, contributes to the
// pooled dot, syncs on a 34-wide per-batch ticket, then merges from registers.
__global__ void __launch_bounds__(192, 2) fused_kernel(
    const float* __restrict__ x,
    const float* __restrict__ W,
    const float* __restrict__ bias,
    float* __restrict__ out) {
    int tid = threadIdx.x;  // 0..191
    int b = blockIdx.x / BPB;
    int m = blockIdx.x % BPB;

    // decode first orbit id m*8 -> (i,j), then step consecutively
    int o = m * OPB, di = 0, cnt = 32;
    while (o >= cnt) { o -= cnt; di++; cnt -= 2; }
    int dj = di + o;

    const float4* xb = (const float4*)(x + (size_t)b * Nn * Cn);
    float4*       ob = (float4*)(out + (size_t)b * Nn * Cn);

    float4 v[OPB][4];
    int lrep[OPB];                 // packed (i<<5)|j per orbit
    float4 ps = {0.f, 0.f, 0.f, 0.f};

#pragma unroll
    for (int q = 0; q < OPB; q++) {
        int i = di, j = dj;
        lrep[q] = (i << 5) | j;
        int l   = (i << 5) | j;
        int tl  = (j << 5) | i;
        int rl  = 1023 - l;
        int rtl = 1023 - tl;
        bool d1 = (i == j);        // tl==l,  rtl==rl
        bool d2 = (j == 31 - i);   // rl==tl, rtl==l

        v[q][0] = __ldcg(&xb[(size_t)l * C4 + tid]);
        v[q][1] = d1 ? v[q][0] : __ldcg(&xb[(size_t)tl * C4 + tid]);
        v[q][2] = d2 ? v[q][1] : __ldcg(&xb[(size_t)rl * C4 + tid]);
        v[q][3] = d1 ? v[q][2] : (d2 ? v[q][0] : __ldcg(&xb[(size_t)rtl * C4 + tid]));

        // pooled partial over DISTINCT rows only
        float w1 = d1 ? 0.f : 1.f;
        float w2 = d2 ? 0.f : 1.f;
        float w3 = (d1 || d2) ? 0.f : 1.f;
        ps.x += v[q][0].x + w1 * v[q][1].x + w2 * v[q][2].x + w3 * v[q][3].x;
        ps.y += v[q][0].y + w1 * v[q][1].y + w2 * v[q][2].y + w3 * v[q][3].y;
        ps.z += v[q][0].z + w1 * v[q][1].z + w2 * v[q][2].z + w3 * v[q][3].z;
        ps.w += v[q][0].w + w1 * v[q][1].w + w2 * v[q][2].w + w3 * v[q][3].w;

        // advance (i, j)
        dj++;
        if (dj > 31 - di) { di++; dj = di; }
    }

    // per-thread dot with W rows (thread owns channels 4*tid..4*tid+3)
    float d[4];
#pragma unroll
    for (int k = 0; k < 4; k++) {
        float4 w4 = __ldg(&((const float4*)W)[k * C4 + tid]);
        d[k] = ps.x * w4.x + ps.y * w4.y + ps.z * w4.z + ps.w * w4.w;
    }
    // block reduce over 6 warps
    __shared__ float sdot[6][4];
    int lane = tid & 31, wid = tid >> 5;
#pragma unroll
    for (int k = 0; k < 4; k++) {
#pragma unroll
        for (int off = 16; off > 0; off >>= 1)
            d[k] += __shfl_down_sync(0xffffffffu, d[k], off);
        if (lane == 0) sdot[wid][k] = d[k];
    }
    __syncthreads();
    if (tid < 32) {
        int k = tid & 3, w = tid >> 2;  // w = 0..7 (pad >5 with 0)
        float vv = (w < 6) ? sdot[w][k] : 0.f;
        vv += __shfl_down_sync(0xffffffffu, vv, 16);
        vv += __shfl_down_sync(0xffffffffu, vv, 8);
        vv += __shfl_down_sync(0xffffffffu, vv, 4);
        if (tid < 4)
            __stcg(&g_pdot[(size_t)blockIdx.x * 4 + tid], vv);
    }

    // ── ticket (acq_rel, no threadfence); last block finalizes alpha[b] ──
    __shared__ int tkt;
    __syncthreads();
    if (tid == 0) {
        int old;
        asm volatile("atom.add.acq_rel.gpu.s32 %0, [%1], 1;"
                     : "=r"(old) : "l"(g_cnt + b) : "memory");
        tkt = old;
    }
    __syncthreads();
    if (tkt == BPB - 1) {
        if (tid < 128) {  // warp k reduces component k over 34 partials
            int k = tid >> 5, ln = tid & 31;
            float s = 0.f;
            if (ln < BPB)
                s = __ldcg(&g_pdot[((size_t)b * BPB + ln) * 4 + k]);
            if (ln + 32 < BPB)
                s += __ldcg(&g_pdot[((size_t)b * BPB + ln + 32) * 4 + k]);
#pragma unroll
            for (int off = 16; off > 0; off >>= 1)
                s += __shfl_down_sync(0xffffffffu, s, off);
            if (ln == 0)
                __stcg(&g_alpha[b * 4 + k], s * (1.0f / 1024.0f) + __ldg(&bias[k]));
        }
        __syncthreads();
        if (tid == 0)
            asm volatile("st.release.gpu.s32 [%0], 1;"
                         :: "l"(g_flag + b) : "memory");
    }

    // ── wait for alpha (data already in registers) ──
    if (tid == 0) {
        int f;
        while (true) {
            asm volatile("ld.acquire.gpu.s32 %0, [%1];"
                         : "=r"(f) : "l"(g_flag + b) : "memory");
            if (f) break;
            __nanosleep(32);
        }
    }
    __syncthreads();

    float c0 = __ldcg(&g_alpha[b * 4 + 0]);
    float c1 = __ldcg(&g_alpha[b * 4 + 1]);
    float c2 = __ldcg(&g_alpha[b * 4 + 2]);
    float c3 = __ldcg(&g_alpha[b * 4 + 3]);

    // ── merge from registers, skip duplicate rows ──
#pragma unroll
    for (int q = 0; q < OPB; q++) {
        int l  = lrep[q];
        int i  = l >> 5, j = l & 31;
        int tl = (j << 5) | i;
        int rl = 1023 - l;
        int rtl = 1023 - tl;
        bool d1 = (i == j);
        bool d2 = (j == 31 - i);
        float4 v0 = v[q][0], v1 = v[q][1], v2 = v[q][2], v3 = v[q][3];
        float4 w;

        w.x = fmaf(c0, v0.x, fmaf(c1, v1.x, fmaf(c2, v2.x, c3 * v3.x)));
        w.y = fmaf(c0, v0.y, fmaf(c1, v1.y, fmaf(c2, v2.y, c3 * v3.y)));
        w.z = fmaf(c0, v0.z, fmaf(c1, v1.z, fmaf(c2, v2.z, c3 * v3.z)));
        w.w = fmaf(c0, v0.w, fmaf(c1, v1.w, fmaf(c2, v2.w, c3 * v3.w)));
        __stcs(&ob[(size_t)l * C4 + tid], w);

        if (!d1) {
            w.x = fmaf(c0, v1.x, fmaf(c1, v0.x, fmaf(c2, v3.x, c3 * v2.x)));
            w.y = fmaf(c0, v1.y, fmaf(c1, v0.y, fmaf(c2, v3.y, c3 * v2.y)));
            w.z = fmaf(c0, v1.z, fmaf(c1, v0.z, fmaf(c2, v3.z, c3 * v2.z)));
            w.w = fmaf(c0, v1.w, fmaf(c1, v0.w, fmaf(c2, v3.w, c3 * v2.w)));
            __stcs(&ob[(size_t)tl * C4 + tid], w);
        }
        if (!d2) {
            w.x = fmaf(c0, v2.x, fmaf(c1, v3.x, fmaf(c2, v0.x, c3 * v1.x)));
            w.y = fmaf(c0, v2.y, fmaf(c1, v3.y, fmaf(c2, v0.y, c3 * v1.y)));
            w.z = fmaf(c0, v2.z, fmaf(c1, v3.z, fmaf(c2, v0.z, c3 * v1.z)));
            w.w = fmaf(c0, v2.w, fmaf(c1, v3.w, fmaf(c2, v0.w, c3 * v1.w)));
            __stcs(&ob[(size_t)rl * C4 + tid], w);
        }
        if (!d1 && !d2) {
            w.x = fmaf(c0, v3.x, fmaf(c1, v2.x, fmaf(c2, v1.x, c3 * v0.x)));
            w.y = fmaf(c0, v3.y, fmaf(c1, v2.y, fmaf(c2, v1.y, c3 * v0.y)));
            w.z = fmaf(c0, v3.z, fmaf(c1, v2.z, fmaf(c2, v1.z, c3 * v0.z)));
            w.w = fmaf(c0, v3.w, fmaf(c1, v2.w, fmaf(c2, v1.w, c3 * v0.w)));
            __stcs(&ob[(size_t)rtl * C4 + tid], w);
        }
    }
}

extern "C" void kernel_launch(void* const* d_in, const int* in_sizes, int n_in,
                              void* d_out, int out_size) {
    const float* x    = (const float*)d_in[0];  // (32,1024,768)
    const float* W    = (const float*)d_in[1];  // (4,768)
    const float* bias = (const float*)d_in[2];  // (4,)
    float* out = (float*)d_out;

    reset_kernel<<<1, 64>>>();
    fused_kernel<<<GRID, 192>>>(x, W, bias, out);
}

// round 7
// speedup vs baseline: 2.1771x; 1.4681x over previous
#include <cuda_runtime.h>

#define Bn 32
#define Nn 1024
#define Cn 768
#define C4 192        // Cn / 4
#define ZCHUNK 32
#define ROWS_PER_Z 32 // Nn / ZCHUNK
#define ORBITS 272

__device__ float g_pdot[Bn * ZCHUNK * 4];  // per-(b,z) partial dot with W
__device__ float g_alpha[Bn * 4];
__device__ int   g_cnt[Bn];

__global__ void reset_kernel() {
    if (threadIdx.x < Bn) g_cnt[threadIdx.x] = 0;
}

// Pass 1 (fused pool + GEMV): grid (Bn, ZCHUNK), block 192.
// Each block: chunk channel-sums -> dot with W -> block reduce -> partial.
// Last block per batch (ticket) reduces the 32 partials and writes alpha[b].
__global__ void __launch_bounds__(192) pool_alpha_kernel(
    const float* __restrict__ x,
    const float* __restrict__ W,
    const float* __restrict__ bias) {
    int b = blockIdx.x;
    int z = blockIdx.y;
    int tid = threadIdx.x;  // 0..191
    const float4* p = (const float4*)(x + ((size_t)b * Nn + (size_t)z * ROWS_PER_Z) * Cn) + tid;

    float4 a0 = {0,0,0,0}, a1 = {0,0,0,0}, a2 = {0,0,0,0}, a3 = {0,0,0,0};
#pragma unroll
    for (int n = 0; n < ROWS_PER_Z; n += 8) {
        float4 v[8];
#pragma unroll
        for (int u = 0; u < 8; u++)
            v[u] = __ldcg(&p[(size_t)(n + u) * C4]);
        a0.x += v[0].x + v[4].x; a0.y += v[0].y + v[4].y;
        a0.z += v[0].z + v[4].z; a0.w += v[0].w + v[4].w;
        a1.x += v[1].x + v[5].x; a1.y += v[1].y + v[5].y;
        a1.z += v[1].z + v[5].z; a1.w += v[1].w + v[5].w;
        a2.x += v[2].x + v[6].x; a2.y += v[2].y + v[6].y;
        a2.z += v[2].z + v[6].z; a2.w += v[2].w + v[6].w;
        a3.x += v[3].x + v[7].x; a3.y += v[3].y + v[7].y;
        a3.z += v[3].z + v[7].z; a3.w += v[3].w + v[7].w;
    }
    float4 s;
    s.x = (a0.x + a1.x) + (a2.x + a3.x);
    s.y = (a0.y + a1.y) + (a2.y + a3.y);
    s.z = (a0.z + a1.z) + (a2.z + a3.z);
    s.w = (a0.w + a1.w) + (a2.w + a3.w);

    // per-thread dot with W rows (thread owns channels 4*tid..4*tid+3)
    float d[4];
#pragma unroll
    for (int k = 0; k < 4; k++) {
        float4 w4 = __ldg(&((const float4*)W)[k * C4 + tid]);
        d[k] = s.x * w4.x + s.y * w4.y + s.z * w4.z + s.w * w4.w;
    }
    __shared__ float sdot[6][4];
    int lane = tid & 31, wid = tid >> 5;
#pragma unroll
    for (int k = 0; k < 4; k++) {
#pragma unroll
        for (int off = 16; off > 0; off >>= 1)
            d[k] += __shfl_down_sync(0xffffffffu, d[k], off);
        if (lane == 0) sdot[wid][k] = d[k];
    }
    __syncthreads();
    if (tid < 32) {
        int k = tid & 3, w = tid >> 2;
        float v = (w < 6) ? sdot[w][k] : 0.f;
        v += __shfl_down_sync(0xffffffffu, v, 16);
        v += __shfl_down_sync(0xffffffffu, v, 8);
        v += __shfl_down_sync(0xffffffffu, v, 4);
        if (tid < 4)
            __stcg(&g_pdot[((size_t)b * ZCHUNK + z) * 4 + k], v);
    }

    // ticket; last chunk block of batch b finalizes alpha[b]
    __shared__ int tkt;
    __syncthreads();
    if (tid == 0) {
        int old;
        asm volatile("atom.add.acq_rel.gpu.s32 %0, [%1], 1;"
                     : "=r"(old) : "l"(g_cnt + b) : "memory");
        tkt = old;
    }
    __syncthreads();
    if (tkt == ZCHUNK - 1) {
        if (tid < 128) {  // warp k reduces component k over 32 partials
            int k = tid >> 5, ln = tid & 31;
            float v = __ldcg(&g_pdot[((size_t)b * ZCHUNK + ln) * 4 + k]);
#pragma unroll
            for (int off = 16; off > 0; off >>= 1)
                v += __shfl_down_sync(0xffffffffu, v, off);
            if (ln == 0)
                __stcg(&g_alpha[b * 4 + k], v * (1.0f / 1024.0f) + __ldg(&bias[k]));
        }
    }
}

// Pass 2: orbit merge. Orbits {l, tl, rl, rtl} partition each batch's rows.
// Degenerate orbits (i==j or j==31-i) skip duplicate loads AND stores.
__global__ void __launch_bounds__(192) merge_kernel(
    const float* __restrict__ x,
    float* __restrict__ out) {
    int bid = blockIdx.x;
    int b = bid / ORBITS;
    int o = bid % ORBITS;
    int i = 0, cnt = 32;
    while (o >= cnt) { o -= cnt; i++; cnt -= 2; }
    int j = i + o;  // i <= j <= 31-i

    int l   = (i << 5) | j;
    int tl  = (j << 5) | i;
    int rl  = 1023 - l;
    int rtl = 1023 - tl;
    bool d1 = (i == j);        // tl==l,  rtl==rl
    bool d2 = (j == 31 - i);   // rl==tl, rtl==l

    float c0 = g_alpha[b * 4 + 0];
    float c1 = g_alpha[b * 4 + 1];
    float c2 = g_alpha[b * 4 + 2];
    float c3 = g_alpha[b * 4 + 3];

    const float4* xb = (const float4*)(x + (size_t)b * Nn * Cn);
    float4*       ob = (float4*)(out + (size_t)b * Nn * Cn);
    int t = threadIdx.x;  // 0..191

    float4 v0 = __ldcg(&xb[(size_t)l * C4 + t]);
    float4 v1 = d1 ? v0 : __ldcg(&xb[(size_t)tl * C4 + t]);
    float4 v2 = d2 ? v1 : __ldcg(&xb[(size_t)rl * C4 + t]);
    float4 v3 = d1 ? v2 : (d2 ? v0 : __ldcg(&xb[(size_t)rtl * C4 + t]));

    float4 w;
    // out[l] = c0 v0 + c1 v1 + c2 v2 + c3 v3
    w.x = fmaf(c0, v0.x, fmaf(c1, v1.x, fmaf(c2, v2.x, c3 * v3.x)));
    w.y = fmaf(c0, v0.y, fmaf(c1, v1.y, fmaf(c2, v2.y, c3 * v3.y)));
    w.z = fmaf(c0, v0.z, fmaf(c1, v1.z, fmaf(c2, v2.z, c3 * v3.z)));
    w.w = fmaf(c0, v0.w, fmaf(c1, v1.w, fmaf(c2, v2.w, c3 * v3.w)));
    __stcs(&ob[(size_t)l * C4 + t], w);

    if (!d1) {  // out[tl] = c0 v1 + c1 v0 + c2 v3 + c3 v2
        w.x = fmaf(c0, v1.x, fmaf(c1, v0.x, fmaf(c2, v3.x, c3 * v2.x)));
        w.y = fmaf(c0, v1.y, fmaf(c1, v0.y, fmaf(c2, v3.y, c3 * v2.y)));
        w.z = fmaf(c0, v1.z, fmaf(c1, v0.z, fmaf(c2, v3.z, c3 * v2.z)));
        w.w = fmaf(c0, v1.w, fmaf(c1, v0.w, fmaf(c2, v3.w, c3 * v2.w)));
        __stcs(&ob[(size_t)tl * C4 + t], w);
    }
    if (!d2) {  // out[rl] = c0 v2 + c1 v3 + c2 v0 + c3 v1
        w.x = fmaf(c0, v2.x, fmaf(c1, v3.x, fmaf(c2, v0.x, c3 * v1.x)));
        w.y = fmaf(c0, v2.y, fmaf(c1, v3.y, fmaf(c2, v0.y, c3 * v1.y)));
        w.z = fmaf(c0, v2.z, fmaf(c1, v3.z, fmaf(c2, v0.z, c3 * v1.z)));
        w.w = fmaf(c0, v2.w, fmaf(c1, v3.w, fmaf(c2, v0.w, c3 * v1.w)));
        __stcs(&ob[(size_t)rl * C4 + t], w);
    }
    if (!d1 && !d2) {  // out[rtl] = c0 v3 + c1 v2 + c2 v1 + c3 v0
        w.x = fmaf(c0, v3.x, fmaf(c1, v2.x, fmaf(c2, v1.x, c3 * v0.x)));
        w.y = fmaf(c0, v3.y, fmaf(c1, v2.y, fmaf(c2, v1.y, c3 * v0.y)));
        w.z = fmaf(c0, v3.z, fmaf(c1, v2.z, fmaf(c2, v1.z, c3 * v0.z)));
        w.w = fmaf(c0, v3.w, fmaf(c1, v2.w, fmaf(c2, v1.w, c3 * v0.w)));
        __stcs(&ob[(size_t)rtl * C4 + t], w);
    }
}

extern "C" void kernel_launch(void* const* d_in, const int* in_sizes, int n_in,
                              void* d_out, int out_size) {
    const float* x    = (const float*)d_in[0];  // (32,1024,768)
    const float* W    = (const float*)d_in[1];  // (4,768)
    const float* bias = (const float*)d_in[2];  // (4,)
    float* out = (float*)d_out;

    reset_kernel<<<1, 32>>>();
    dim3 g1(Bn, ZCHUNK);
    pool_alpha_kernel<<<g1, 192>>>(x, W, bias);
    merge_kernel<<<Bn * ORBITS, 192>>>(x, out);
}